// round 14
// baseline (speedup 1.0000x reference)
#include <cuda_runtime.h>

#define BB  64
#define INN 512
#define HH  512
#define HID 16

// ---------------- packed f32x2 helpers (Blackwell sm_100+) ----------------
typedef unsigned long long u64;

static __device__ __forceinline__ u64 f2_fma(u64 a, u64 b, u64 c) {
    u64 r;
    asm("fma.rn.f32x2 %0, %1, %2, %3;" : "=l"(r) : "l"(a), "l"(b), "l"(c));
    return r;
}
static __device__ __forceinline__ u64 f2_add(u64 a, u64 b) {
    u64 r;
    asm("add.rn.f32x2 %0, %1, %2;" : "=l"(r) : "l"(a), "l"(b));
    return r;
}
static __device__ __forceinline__ u64 f2_pack(float x, float y) {
    u64 r;
    asm("mov.b64 %0, {%1, %2};" : "=l"(r) : "f"(x), "f"(y));
    return r;
}
static __device__ __forceinline__ float2 f2_unpack(u64 v) {
    float2 r;
    asm("mov.b64 {%0, %1}, %2;" : "=f"(r.x), "=f"(r.y) : "l"(v));
    return r;
}
// relu: pack/unpack are register aliasing (free); 2x FMNMX on the alu pipe.
static __device__ __forceinline__ u64 f2_relu(u64 v) {
    float2 t = f2_unpack(v);
    return f2_pack(fmaxf(t.x, 0.0f), fmaxf(t.y, 0.0f));
}

// ---------------- fused kernel, j-paired lanes + prefetch ----------------
// out[i,j] = (1/B) * sum_b sum_k relu(pre[b,i]*u_k + post[b,j]*v_k + w_ij*t_k + b1_k) * W2_k + b2
//
// R14 on top of R13 (46.9us):
//  1. Cross-iteration PREFETCH: iteration's math consumes loads issued the
//     previous iteration; next loads (index (b+2)&63, wraps in-bounds) issue
//     before the math, hiding the ~39cyc L1 hit under ~80cyc of math issue.
//  2. W2 factored OUT of the b-loop: acc[k] = sum_b relu(x) (ADD2, same fma
//     pipe cost); fold grand += acc[k]*W2_k once per chunk. Removes w2_bb
//     from loop constants (-8 regs), paying for the 6 prefetch regs.
// Structure otherwise R13: 1i x 2j tile (lanes = j-pair), k-quarter chunks,
// b x 2 unroll, single kernel, grid (4,256)=1024 blocks, one wave.
__global__ __launch_bounds__(128, 8)
void plasticity_fused(const float* __restrict__ pre,
                      const float* __restrict__ post,
                      const float* __restrict__ weight,
                      const float* __restrict__ W1,
                      const float* __restrict__ b1,
                      const float* __restrict__ W2,
                      const float* __restrict__ b2,
                      float* __restrict__ out) {
    const int tj = threadIdx.x & 63;       // 0..63
    const int ti = threadIdx.x >> 6;       // 0..1 (warp-uniform)
    const int i  = blockIdx.y * 2 + ti;
    const int j0 = blockIdx.x * 128 + tj * 2;

    // w_(i,j0), w_(i,j0+1) as a natural 64-bit pair (8B-aligned: j0 even).
    const u64 wpair = *reinterpret_cast<const u64*>(&weight[(size_t)i * HH + j0]);

    const float* pre_b  = pre + i;                            // stride INN over b
    const u64*   post_b = reinterpret_cast<const u64*>(post + j0);  // stride HH/2 over b

    u64 grand = 0ull;    // sum_k W2_k * sum_b relu(...), lanes = (j0, j0+1)

#pragma unroll 1
    for (int chunk = 0; chunk < 4; ++chunk) {
        const int k0 = chunk * 4;
        // Per-chunk constants (hoisted out of the b-loop): 12 pairs = 24 regs.
        u64 u_bb[4], v_bb[4], d[4];
#pragma unroll
        for (int kk = 0; kk < 4; ++kk) {
            const int k = k0 + kk;
            const float uk = W1[k * 3 + 0];
            const float vk = W1[k * 3 + 1];
            const float tk = W1[k * 3 + 2];
            u_bb[kk] = f2_pack(uk, uk);
            v_bb[kk] = f2_pack(vk, vk);
            const u64 t_bb  = f2_pack(tk, tk);
            const u64 b1_bb = f2_pack(b1[k], b1[k]);
            d[kk] = f2_fma(wpair, t_bb, b1_bb);    // w_ij * t_k + b1_k (pair)
        }

        // 4 accumulator chains: acc[kk] = sum_b relu(...), W2 folded later.
        u64 acc[4] = { 0ull, 0ull, 0ull, 0ull };

        // Prefetch b = 0, 1.
        float pf_p0 = pre_b[0];
        float pf_p1 = pre_b[INN];
        u64   pf_q0 = post_b[0];
        u64   pf_q1 = post_b[HH / 2];

#pragma unroll 1
        for (int b = 0; b < BB; b += 2) {
            // Consume previously-issued loads; issue next pair's loads first.
            const float cp0 = pf_p0;
            const float cp1 = pf_p1;
            const u64   q0  = pf_q0;
            const u64   q1  = pf_q1;
            const int bn = (b + 2) & (BB - 1);   // wraps to 0 (in-bounds reload)
            pf_p0 = pre_b[(size_t)bn * INN];
            pf_p1 = pre_b[(size_t)bn * INN + INN];
            pf_q0 = post_b[(size_t)bn * (HH / 2)];
            pf_q1 = post_b[(size_t)bn * (HH / 2) + HH / 2];

            const u64 pre0 = f2_pack(cp0, cp0);
            const u64 pre1 = f2_pack(cp1, cp1);

            // ---- b even ----
#pragma unroll
            for (int kk = 0; kk < 4; ++kk) {
                u64 x = f2_fma(q0, v_bb[kk], d[kk]);     // post*v + (w*t+b1)
                x = f2_fma(pre0, u_bb[kk], x);           // + pre*u
                acc[kk] = f2_add(acc[kk], f2_relu(x));   // += relu
            }
            // ---- b odd ----
#pragma unroll
            for (int kk = 0; kk < 4; ++kk) {
                u64 x = f2_fma(q1, v_bb[kk], d[kk]);
                x = f2_fma(pre1, u_bb[kk], x);
                acc[kk] = f2_add(acc[kk], f2_relu(x));
            }
        }

        // Fold this chunk: grand += acc[kk] * W2_k (4 fma, once per chunk).
#pragma unroll
        for (int kk = 0; kk < 4; ++kk) {
            const float w2k = W2[k0 + kk];
            grand = f2_fma(acc[kk], f2_pack(w2k, w2k), grand);
        }
    }

    // Epilogue: scale by 1/B, add bias, store the j-pair as 64-bit.
    const float inv_b = 1.0f / (float)BB;
    const float bias2 = b2[0];
    u64 res = f2_fma(grand, f2_pack(inv_b, inv_b), f2_pack(bias2, bias2));
    *reinterpret_cast<u64*>(&out[(size_t)i * HH + j0]) = res;
}

// ---------------- launch ----------------
extern "C" void kernel_launch(void* const* d_in, const int* in_sizes, int n_in,
                              void* d_out, int out_size) {
    const float* pre    = (const float*)d_in[0];
    const float* post   = (const float*)d_in[1];
    const float* weight = (const float*)d_in[2];
    const float* W1     = (const float*)d_in[3];
    const float* b1     = (const float*)d_in[4];
    const float* W2     = (const float*)d_in[5];
    const float* b2     = (const float*)d_in[6];
    float* out = (float*)d_out;

    plasticity_fused<<<dim3(HH / 128, INN / 2), 128>>>(
        pre, post, weight, W1, b1, W2, b2, out);
}

// round 15
// speedup vs baseline: 1.1918x; 1.1918x over previous
#include <cuda_runtime.h>

#define BB  64
#define INN 512
#define HH  512
#define HID 16

// ---------------- packed f32x2 helpers (Blackwell sm_100+) ----------------
typedef unsigned long long u64;

static __device__ __forceinline__ u64 f2_fma(u64 a, u64 b, u64 c) {
    u64 r;
    asm("fma.rn.f32x2 %0, %1, %2, %3;" : "=l"(r) : "l"(a), "l"(b), "l"(c));
    return r;
}
static __device__ __forceinline__ u64 f2_add(u64 a, u64 b) {
    u64 r;
    asm("add.rn.f32x2 %0, %1, %2;" : "=l"(r) : "l"(a), "l"(b));
    return r;
}
static __device__ __forceinline__ u64 f2_pack(float x, float y) {
    u64 r;
    asm("mov.b64 %0, {%1, %2};" : "=l"(r) : "f"(x), "f"(y));
    return r;
}
static __device__ __forceinline__ float2 f2_unpack(u64 v) {
    float2 r;
    asm("mov.b64 {%0, %1}, %2;" : "=f"(r.x), "=f"(r.y) : "l"(v));
    return r;
}
// relu: pack/unpack are register aliasing (free); 2x FMNMX on the alu pipe.
static __device__ __forceinline__ u64 f2_relu(u64 v) {
    float2 t = f2_unpack(v);
    return f2_pack(fmaxf(t.x, 0.0f), fmaxf(t.y, 0.0f));
}

// ---------------- fused kernel, j-paired lanes ----------------
// out[i,j] = (1/B) * sum_b sum_k relu(pre[b,i]*u_k + post[b,j]*v_k + w_ij*t_k + b1_k) * W2_k + b2
//
// R15 = R13 base (prefetch REVERTED -- R14 showed indexed-address prefetch
// adds more ALU issues than it hides; pointer-increment + immediate-offset
// loads were already covered) + two changes:
//  1. acc split by b-parity: acc[2][4] = 8 truly independent chains.
//     (R13 shared acc[kk] between the b-even and b-odd bodies, serializing
//      them into 4 chains of length 2 -- the real per-iteration critical path.)
//  2. W2 factored out of the b-loop: acc += relu (ADD2, same fma pipe);
//     grand += acc*W2 folded once per chunk. -8 const regs pays for +8 acc.
// Structure: 1i x 2j tile (lanes = j-pair), k-quarter chunks, b x 2 unroll,
// grid (4,256) = 1024 blocks, one wave at <=64 regs.
__global__ __launch_bounds__(128, 8)
void plasticity_fused(const float* __restrict__ pre,
                      const float* __restrict__ post,
                      const float* __restrict__ weight,
                      const float* __restrict__ W1,
                      const float* __restrict__ b1,
                      const float* __restrict__ W2,
                      const float* __restrict__ b2,
                      float* __restrict__ out) {
    const int tj = threadIdx.x & 63;       // 0..63
    const int ti = threadIdx.x >> 6;       // 0..1 (warp-uniform)
    const int i  = blockIdx.y * 2 + ti;
    const int j0 = blockIdx.x * 128 + tj * 2;

    // w_(i,j0), w_(i,j0+1) as a natural 64-bit pair (8B-aligned: j0 even).
    const u64 wpair = *reinterpret_cast<const u64*>(&weight[(size_t)i * HH + j0]);

    u64 grand = 0ull;    // sum_k W2_k * sum_b relu(...), lanes = (j0, j0+1)

#pragma unroll 1
    for (int chunk = 0; chunk < 4; ++chunk) {
        const int k0 = chunk * 4;
        // Per-chunk constants (hoisted out of the b-loop): 12 pairs = 24 regs.
        u64 u_bb[4], v_bb[4], d[4];
#pragma unroll
        for (int kk = 0; kk < 4; ++kk) {
            const int k = k0 + kk;
            const float uk = W1[k * 3 + 0];
            const float vk = W1[k * 3 + 1];
            const float tk = W1[k * 3 + 2];
            u_bb[kk] = f2_pack(uk, uk);
            v_bb[kk] = f2_pack(vk, vk);
            const u64 t_bb  = f2_pack(tk, tk);
            const u64 b1_bb = f2_pack(b1[k], b1[k]);
            d[kk] = f2_fma(wpair, t_bb, b1_bb);    // w_ij * t_k + b1_k (pair)
        }

        // 8 independent accumulator chains: [b-parity][kk].
        u64 acc[2][4] = { {0ull,0ull,0ull,0ull}, {0ull,0ull,0ull,0ull} };

        const float* pp = pre + i;                                  // +2*INN/iter
        const u64*   qq = reinterpret_cast<const u64*>(post + j0);  // +HH u64/iter

#pragma unroll 1
        for (int b = 0; b < BB; b += 2) {
            // Batched loads, immediate offsets, pointer increment (R13 style).
            const float cp0 = pp[0];
            const float cp1 = pp[INN];
            const u64   q0  = qq[0];              // (post[b,j0], post[b,j0+1])
            const u64   q1  = qq[HH / 2];         // next b row
            pp += 2 * INN;
            qq += HH;

            const u64 pre0 = f2_pack(cp0, cp0);
            const u64 pre1 = f2_pack(cp1, cp1);

            // ---- b even ----
#pragma unroll
            for (int kk = 0; kk < 4; ++kk) {
                u64 x = f2_fma(q0, v_bb[kk], d[kk]);       // post*v + (w*t+b1)
                x = f2_fma(pre0, u_bb[kk], x);             // + pre*u
                acc[0][kk] = f2_add(acc[0][kk], f2_relu(x));
            }
            // ---- b odd (independent acc bank) ----
#pragma unroll
            for (int kk = 0; kk < 4; ++kk) {
                u64 x = f2_fma(q1, v_bb[kk], d[kk]);
                x = f2_fma(pre1, u_bb[kk], x);
                acc[1][kk] = f2_add(acc[1][kk], f2_relu(x));
            }
        }

        // Fold this chunk: grand += (acc_even + acc_odd) * W2_k.
#pragma unroll
        for (int kk = 0; kk < 4; ++kk) {
            const float w2k = W2[k0 + kk];
            grand = f2_fma(f2_add(acc[0][kk], acc[1][kk]),
                           f2_pack(w2k, w2k), grand);
        }
    }

    // Epilogue: scale by 1/B, add bias, store the j-pair as 64-bit.
    const float inv_b = 1.0f / (float)BB;
    const float bias2 = b2[0];
    u64 res = f2_fma(grand, f2_pack(inv_b, inv_b), f2_pack(bias2, bias2));
    *reinterpret_cast<u64*>(&out[(size_t)i * HH + j0]) = res;
}

// ---------------- launch ----------------
extern "C" void kernel_launch(void* const* d_in, const int* in_sizes, int n_in,
                              void* d_out, int out_size) {
    const float* pre    = (const float*)d_in[0];
    const float* post   = (const float*)d_in[1];
    const float* weight = (const float*)d_in[2];
    const float* W1     = (const float*)d_in[3];
    const float* b1     = (const float*)d_in[4];
    const float* W2     = (const float*)d_in[5];
    const float* b2     = (const float*)d_in[6];
    float* out = (float*)d_out;

    plasticity_fused<<<dim3(HH / 128, INN / 2), 128>>>(
        pre, post, weight, W1, b1, W2, b2, out);
}